// round 1
// baseline (speedup 1.0000x reference)
#include <cuda_runtime.h>
#include <stdint.h>

// Problem constants
#define DX 128
#define DY 128
#define DZ 128
#define VOX (DX * DY * DZ)        // 2,097,152 voxels per batch grid
#define BATCH 4
#define NPTS 262144               // points per batch per cloud
#define PER_CLOUD (BATCH * NPTS)  // 1,048,576 points per cloud
#define TOTAL_PTS (2 * PER_CLOUD) // 2,097,152

// ---------------------------------------------------------------------------
// Zero-fill d_out (poisoned to 0xAA by harness). 16,777,216 floats = 4,194,304
// float4 stores.
// ---------------------------------------------------------------------------
__global__ void zero_out_kernel(float4* __restrict__ out, int n4) {
    int i = blockIdx.x * blockDim.x + threadIdx.x;
    if (i < n4) out[i] = make_float4(0.f, 0.f, 0.f, 0.f);
}

// ---------------------------------------------------------------------------
// Trilinear splat: one thread per point. 8 atomicAdds (REDG, no-return path).
// out layout: [cloud(2)][batch(4)][VOX] floats.
// ---------------------------------------------------------------------------
__global__ void splat_kernel(const float* __restrict__ pred,
                             const float* __restrict__ gt,
                             float* __restrict__ out) {
    int tid = blockIdx.x * blockDim.x + threadIdx.x;
    if (tid >= TOTAL_PTS) return;

    int cloud = (tid >= PER_CLOUD) ? 1 : 0;
    int rem = tid - cloud * PER_CLOUD;            // point index within cloud
    const float* __restrict__ src = cloud ? gt : pred;

    // load point (stride-3 layout; 3 scalar LDGs)
    float px = src[rem * 3 + 0] * 64.0f;          // Dx/2 = 64
    float py = src[rem * 3 + 1] * 64.0f;
    float pz = src[rem * 3 + 2] * 64.0f;

    float flx = floorf(px);
    float fly = floorf(py);
    float flz = floorf(pz);

    float dx = px - flx;                          // frac in [0,1)
    float dy = py - fly;
    float dz = pz - flz;
    float ex = 1.0f - dx;
    float ey = 1.0f - dy;
    float ez = 1.0f - dz;

    int ix = (int)flx + (DX / 2);                 // lower corner index, grid coords
    int iy = (int)fly + (DY / 2);
    int iz = (int)flz + (DZ / 2);

    int b = rem >> 18;                            // rem / NPTS (NPTS = 2^18)
    float* __restrict__ o = out + ((size_t)(cloud * BATCH + b)) * VOX;

    // Fast path: entire 2x2x2 stencil in-bounds (guaranteed by input range).
    if ((unsigned)ix < (unsigned)(DX - 1) &&
        (unsigned)iy < (unsigned)(DY - 1) &&
        (unsigned)iz < (unsigned)(DZ - 1)) {
        int base = (ix * DY + iy) * DZ + iz;
        float wx0y0 = ex * ey;
        float wx0y1 = ex * dy;
        float wx1y0 = dx * ey;
        float wx1y1 = dx * dy;
        atomicAdd(o + base,                wx0y0 * ez);
        atomicAdd(o + base + 1,            wx0y0 * dz);
        atomicAdd(o + base + DZ,           wx0y1 * ez);
        atomicAdd(o + base + DZ + 1,       wx0y1 * dz);
        atomicAdd(o + base + DY * DZ,          wx1y0 * ez);
        atomicAdd(o + base + DY * DZ + 1,      wx1y0 * dz);
        atomicAdd(o + base + DY * DZ + DZ,     wx1y1 * ez);
        atomicAdd(o + base + DY * DZ + DZ + 1, wx1y1 * dz);
    } else {
        // Slow path: per-corner validity (matches reference semantics).
        #pragma unroll
        for (int c = 0; c < 8; c++) {
            int ox = (c >> 2) & 1, oy = (c >> 1) & 1, oz = c & 1;
            int jx = ix + ox, jy = iy + oy, jz = iz + oz;
            if ((unsigned)jx < DX && (unsigned)jy < DY && (unsigned)jz < DZ) {
                float w = (ox ? dx : ex) * (oy ? dy : ey) * (oz ? dz : ez);
                atomicAdd(o + ((jx * DY + jy) * DZ + jz), w);
            }
        }
    }
}

extern "C" void kernel_launch(void* const* d_in, const int* in_sizes, int n_in,
                              void* d_out, int out_size) {
    const float* pred = (const float*)d_in[0];
    const float* gt   = (const float*)d_in[1];
    float* out = (float*)d_out;

    // zero-fill output (out_size = 2 * 4 * VOX = 16,777,216 floats)
    int n4 = out_size / 4;
    zero_out_kernel<<<(n4 + 255) / 256, 256>>>((float4*)out, n4);

    // splat both clouds
    splat_kernel<<<(TOTAL_PTS + 255) / 256, 256>>>(pred, gt, out);
}

// round 2
// speedup vs baseline: 1.4301x; 1.4301x over previous
#include <cuda_runtime.h>
#include <stdint.h>

// Problem constants
#define DX 128
#define DY 128
#define DZ 128
#define VOX (DX * DY * DZ)        // 2,097,152 voxels per batch grid
#define BATCH 4
#define NPTS 262144               // points per batch per cloud
#define PER_CLOUD (BATCH * NPTS)  // 1,048,576 points per cloud
#define TOTAL_PTS (2 * PER_CLOUD) // 2,097,152

// ---------------------------------------------------------------------------
// Vector / scalar global float reductions (no return -> REDG path).
// red.global.add.v4.f32 requires 16B-aligned address (sm_90+).
// ---------------------------------------------------------------------------
__device__ __forceinline__ void red4(float* p, float a, float b, float c, float d) {
    asm volatile("red.global.add.v4.f32 [%0], {%1, %2, %3, %4};"
                 :: "l"(p), "f"(a), "f"(b), "f"(c), "f"(d) : "memory");
}
__device__ __forceinline__ void red1(float* p, float a) {
    asm volatile("red.global.add.f32 [%0], %1;" :: "l"(p), "f"(a) : "memory");
}

// ---------------------------------------------------------------------------
// Zero-fill d_out (poisoned to 0xAA by harness).
// ---------------------------------------------------------------------------
__global__ void zero_out_kernel(float4* __restrict__ out, int n4) {
    int i = blockIdx.x * blockDim.x + threadIdx.x;
    if (i < n4) out[i] = make_float4(0.f, 0.f, 0.f, 0.f);
}

// ---------------------------------------------------------------------------
// Trilinear splat: one thread per point.
// Each z-pair (columns iz, iz+1) is merged into ONE red.v4 sector transaction
// when it fits inside a 16B-aligned window (q = iz&3 < 3). Zero lanes are
// harmless (+0.0 adds; grid values are non-negative sums).
// out layout: [cloud(2)][batch(4)][VOX] floats.
// ---------------------------------------------------------------------------
__global__ void splat_kernel(const float* __restrict__ pred,
                             const float* __restrict__ gt,
                             float* __restrict__ out) {
    int tid = blockIdx.x * blockDim.x + threadIdx.x;
    if (tid >= TOTAL_PTS) return;

    int cloud = (tid >= PER_CLOUD) ? 1 : 0;
    int rem = tid - cloud * PER_CLOUD;
    const float* __restrict__ src = cloud ? gt : pred;

    float px = src[rem * 3 + 0] * 64.0f;
    float py = src[rem * 3 + 1] * 64.0f;
    float pz = src[rem * 3 + 2] * 64.0f;

    float flx = floorf(px);
    float fly = floorf(py);
    float flz = floorf(pz);

    float dx = px - flx;
    float dy = py - fly;
    float dz = pz - flz;
    float ex = 1.0f - dx;
    float ey = 1.0f - dy;
    float ez = 1.0f - dz;

    int ix = (int)flx + (DX / 2);
    int iy = (int)fly + (DY / 2);
    int iz = (int)flz + (DZ / 2);

    int b = rem >> 18;  // rem / NPTS
    float* __restrict__ o = out + ((size_t)(cloud * BATCH + b)) * VOX;

    if ((unsigned)ix < (unsigned)(DX - 1) &&
        (unsigned)iy < (unsigned)(DY - 1) &&
        (unsigned)iz < (unsigned)(DZ - 1)) {
        // row base offsets and row weights
        int r0 = (ix * DY + iy) * DZ;
        float w0 = ex * ey;   // (ix,   iy  )
        float w1 = ex * dy;   // (ix,   iy+1)
        float w2 = dx * ey;   // (ix+1, iy  )
        float w3 = dx * dy;   // (ix+1, iy+1)
        int rows[4] = { r0, r0 + DZ, r0 + DY * DZ, r0 + DY * DZ + DZ };
        float ws[4]  = { w0, w1, w2, w3 };

        int q = iz & 3;
        int a = iz & ~3;

        if (q < 3) {
            #pragma unroll
            for (int r = 0; r < 4; r++) {
                float lo = ws[r] * ez;
                float hi = ws[r] * dz;
                float v0 = (q == 0) ? lo : 0.0f;
                float v1 = (q == 0) ? hi : ((q == 1) ? lo : 0.0f);
                float v2 = (q == 1) ? hi : ((q == 2) ? lo : 0.0f);
                float v3 = (q == 2) ? hi : 0.0f;
                red4(o + rows[r] + a, v0, v1, v2, v3);
            }
        } else {
            #pragma unroll
            for (int r = 0; r < 4; r++) {
                red1(o + rows[r] + iz,     ws[r] * ez);
                red1(o + rows[r] + iz + 1, ws[r] * dz);
            }
        }
    } else {
        // Slow path: per-corner validity (matches reference semantics).
        #pragma unroll
        for (int c = 0; c < 8; c++) {
            int ox = (c >> 2) & 1, oy = (c >> 1) & 1, oz = c & 1;
            int jx = ix + ox, jy = iy + oy, jz = iz + oz;
            if ((unsigned)jx < DX && (unsigned)jy < DY && (unsigned)jz < DZ) {
                float w = (ox ? dx : ex) * (oy ? dy : ey) * (oz ? dz : ez);
                red1(o + ((jx * DY + jy) * DZ + jz), w);
            }
        }
    }
}

extern "C" void kernel_launch(void* const* d_in, const int* in_sizes, int n_in,
                              void* d_out, int out_size) {
    const float* pred = (const float*)d_in[0];
    const float* gt   = (const float*)d_in[1];
    float* out = (float*)d_out;

    int n4 = out_size / 4;
    zero_out_kernel<<<(n4 + 255) / 256, 256>>>((float4*)out, n4);
    splat_kernel<<<(TOTAL_PTS + 255) / 256, 256>>>(pred, gt, out);
}